// round 2
// baseline (speedup 1.0000x reference)
#include <cuda_runtime.h>
#include <cuda_bf16.h>

// Problem constants
#define BATCH   64
#define CHAN    256
#define HWSZ    1024          // 32*32
#define NROWS   65536         // BATCH*HWSZ
#define KCODES  1024
#define TILE_R  128           // rows per CTA in main kernel
#define TILE_K  128           // codes per k-chunk
#define CI      16            // inner-dim chunk
#define NTILES  512           // NROWS / TILE_R
#define NPART   8192          // 512 tiles * 16 channel-groups

// Scratch (device globals: no allocation allowed)
__device__ float g_esq[KCODES];
__device__ float g_zsq[NROWS];
__device__ int   g_idx[NROWS];
__device__ float g_part[NPART];

// ---------------------------------------------------------------------------
// e_sq[k] = sum_c emb[k,c]^2, sequential-c fp32 FMA chain (mimic reference).
// ---------------------------------------------------------------------------
__global__ void k_esq(const float* __restrict__ emb) {
    int k = blockIdx.x * blockDim.x + threadIdx.x;
    if (k < KCODES) {
        const float* row = emb + (size_t)k * CHAN;
        float acc = 0.0f;
        #pragma unroll 8
        for (int c = 0; c < CHAN; ++c) acc = fmaf(row[c], row[c], acc);
        g_esq[k] = acc;
    }
}

// ---------------------------------------------------------------------------
// z_sq[n] = sum_c z[n,c]^2, sequential-c fp32 FMA chain.
// grid = 512 tiles, 128 threads; thread r owns row (tile*128 + r).
// Loads are coalesced across r for each c.
// ---------------------------------------------------------------------------
__global__ void k_zsq(const float* __restrict__ z) {
    int t   = blockIdx.x;
    int b   = t >> 3;
    int hw0 = (t & 7) << 7;
    int r   = threadIdx.x;                  // 0..127
    const float* base = z + (size_t)b * CHAN * HWSZ + hw0 + r;
    float acc = 0.0f;
    #pragma unroll 8
    for (int c = 0; c < CHAN; ++c) {
        float v = base[(size_t)c * HWSZ];
        acc = fmaf(v, v, acc);
    }
    g_zsq[t * TILE_R + r] = acc;
}

// ---------------------------------------------------------------------------
// Main: per-row argmin over K codes of dist = (z_sq + e_sq) - 2*(z.e)
// z.e accumulated as a single sequential fp32 FMA chain over c = 0..255
// (matches reference rounding domain; ties broken toward lowest k, matching
// jnp.argmin first-occurrence semantics).
// CTA: 256 threads as 16x16; each thread owns an 8x8 (row x code) micro-tile.
// ---------------------------------------------------------------------------
__global__ void __launch_bounds__(256, 2)
k_main(const float* __restrict__ z, const float* __restrict__ emb) {
    __shared__ float Zs[CI][TILE_R + 4];   // [ci][row]
    __shared__ float Es[CI][TILE_K + 4];   // [ci][code]
    __shared__ float cd[TILE_R][17];
    __shared__ int   ck[TILE_R][17];

    int t   = blockIdx.x;
    int b   = t >> 3;
    int hw0 = (t & 7) << 7;
    int tid = threadIdx.x;
    int tx  = tid & 15;
    int ty  = tid >> 4;

    float bestd[8];
    int   bestk[8];
    #pragma unroll
    for (int i = 0; i < 8; ++i) { bestd[i] = 3.4028235e38f; bestk[i] = 0; }

    float zsqr[8];
    #pragma unroll
    for (int i = 0; i < 8; ++i) zsqr[i] = g_zsq[t * TILE_R + ty * 8 + i];

    const float* zbase = z + (size_t)b * CHAN * HWSZ + hw0;

    for (int kc = 0; kc < KCODES; kc += TILE_K) {
        float acc[8][8];
        #pragma unroll
        for (int i = 0; i < 8; ++i)
            #pragma unroll
            for (int j = 0; j < 8; ++j) acc[i][j] = 0.0f;

        for (int cc = 0; cc < CHAN; cc += CI) {
            // Load Z chunk [CI][128]: coalesced along rows.
            {
                int rZ  = tid & 127;
                int ciZ = tid >> 7;            // 0/1
                #pragma unroll
                for (int p = 0; p < 8; ++p) {
                    int ci = p * 2 + ciZ;
                    Zs[ci][rZ] = zbase[(size_t)(cc + ci) * HWSZ + rZ];
                }
            }
            // Load E chunk transposed [CI][128 codes].
            {
                int ciE = tid & 15;
                int kkE = tid >> 4;            // 0..15
                #pragma unroll
                for (int p = 0; p < 8; ++p) {
                    int kk = p * 16 + kkE;
                    Es[ciE][kk] = emb[(size_t)(kc + kk) * CHAN + cc + ciE];
                }
            }
            __syncthreads();

            #pragma unroll
            for (int ci = 0; ci < CI; ++ci) {
                float zr[8], er[8];
                #pragma unroll
                for (int i = 0; i < 8; ++i) zr[i] = Zs[ci][ty * 8 + i];
                #pragma unroll
                for (int j = 0; j < 8; ++j) er[j] = Es[ci][tx * 8 + j];
                #pragma unroll
                for (int i = 0; i < 8; ++i)
                    #pragma unroll
                    for (int j = 0; j < 8; ++j)
                        acc[i][j] = fmaf(zr[i], er[j], acc[i][j]);
            }
            __syncthreads();
        }

        // Fold this k-chunk into the running argmin. Strict '<' keeps the
        // earliest k on exact fp32 ties (j and kc ascend per thread).
        #pragma unroll
        for (int j = 0; j < 8; ++j) {
            int k = kc + tx * 8 + j;
            float es = g_esq[k];
            #pragma unroll
            for (int i = 0; i < 8; ++i) {
                float d = (zsqr[i] + es) - 2.0f * acc[i][j];
                if (d < bestd[i]) { bestd[i] = d; bestk[i] = k; }
            }
        }
    }

    // Cross-thread reduction: lexicographic (d, k) min = first occurrence of
    // the fp32 minimum (jnp.argmin semantics).
    #pragma unroll
    for (int i = 0; i < 8; ++i) {
        cd[ty * 8 + i][tx] = bestd[i];
        ck[ty * 8 + i][tx] = bestk[i];
    }
    __syncthreads();
    if (tid < TILE_R) {
        float bd = cd[tid][0];
        int   bk = ck[tid][0];
        #pragma unroll
        for (int x = 1; x < 16; ++x) {
            float d  = cd[tid][x];
            int   k2 = ck[tid][x];
            if (d < bd || (d == bd && k2 < bk)) { bd = d; bk = k2; }
        }
        g_idx[t * TILE_R + tid] = bk;
    }
}

// ---------------------------------------------------------------------------
// Output + loss partials: out[b,c,hw] = emb[idx[n], c]; accumulate (q-z)^2.
// grid = (512 tiles, 16 channel-groups), 256 threads, deterministic reduce.
// ---------------------------------------------------------------------------
__global__ void k_out(const float* __restrict__ z, const float* __restrict__ emb,
                      float* __restrict__ out) {
    __shared__ int   sidx[TILE_R];
    __shared__ float red[256];

    int t   = blockIdx.x;      // tile over rows
    int cy  = blockIdx.y;      // channel group (16 channels each)
    int b   = t >> 3;
    int hw0 = (t & 7) << 7;
    int tid = threadIdx.x;

    if (tid < TILE_R) sidx[tid] = g_idx[t * TILE_R + tid];
    __syncthreads();

    int r  = tid & 127;
    int ch = tid >> 7;         // 0/1
    float accum = 0.0f;
    #pragma unroll
    for (int p = 0; p < 8; ++p) {
        int c = cy * 16 + p * 2 + ch;
        size_t off = ((size_t)b * CHAN + c) * HWSZ + hw0 + r;
        float q  = emb[(size_t)sidx[r] * CHAN + c];
        float zv = z[off];
        out[off] = q;
        float df = q - zv;
        accum = fmaf(df, df, accum);
    }
    red[tid] = accum;
    __syncthreads();
    #pragma unroll
    for (int s = 128; s > 0; s >>= 1) {
        if (tid < s) red[tid] += red[tid + s];
        __syncthreads();
    }
    if (tid == 0) g_part[cy * NTILES + t] = red[0];
}

// loss = (1 + BETA) * mean((z_q - z)^2); fixed-order reduction (deterministic)
__global__ void k_final(float* __restrict__ out) {
    __shared__ float red[256];
    int tid = threadIdx.x;
    float a = 0.0f;
    for (int i = tid; i < NPART; i += 256) a += g_part[i];
    red[tid] = a;
    __syncthreads();
    #pragma unroll
    for (int s = 128; s > 0; s >>= 1) {
        if (tid < s) red[tid] += red[tid + s];
        __syncthreads();
    }
    if (tid == 0) out[16777216] = 1.25f * (red[0] / 16777216.0f);
}

// ---------------------------------------------------------------------------
extern "C" void kernel_launch(void* const* d_in, const int* in_sizes, int n_in,
                              void* d_out, int out_size) {
    const float* z   = (const float*)d_in[0];   // [64,256,32,32]
    const float* emb = (const float*)d_in[1];   // [1024,256]
    float* out = (float*)d_out;                 // 16777216 z_q + 1 loss

    k_esq<<<8, 128>>>(emb);
    k_zsq<<<NTILES, 128>>>(z);
    k_main<<<NTILES, 256>>>(z, emb);
    dim3 g(NTILES, 16);
    k_out<<<g, 256>>>(z, emb, out);
    k_final<<<1, 256>>>(out);
}

// round 6
// speedup vs baseline: 1.5050x; 1.5050x over previous
#include <cuda_runtime.h>
#include <cuda_bf16.h>
#include <cstdint>

// ---------------------------------------------------------------------------
// Problem constants
#define BATCH   64
#define CHAN    256
#define HWSZ    1024
#define NROWS   65536
#define KCODES  1024
#define TILE_R  128
#define NTILES  512
#define NPART   2048
#define EPS_CAND 2e-3f
#define CANDCAP  16
#define FLT_BIG  3.4028235e38f

// SMEM layout (relative to 1024-aligned base)
#define A_OFF    0          // 128 rows x 256 c bf16, swizzled: 65536 B
#define BBUF_OFF 65536      // two B buffers, 65536 B each (also A-stage scratch)
#define ESQ_OFF  196608     // 1024 f32
#define ZSQ_OFF  200704     // 128 f32
#define CNT_OFF  201216     // 128 int
#define CAND_OFF 201728     // 128*16 int = 8192 B
#define SMEM_END 209920
#define SMEM_REQ (SMEM_END + 1024)

// ---------------------------------------------------------------------------
// Scratch (static device globals; no runtime allocation)
__device__ float g_esq[KCODES];
__device__ float g_zsq[NROWS];
__device__ int   g_idx[NROWS];
__device__ float g_part[NPART];
__device__ int   g_cnt[NROWS];
__device__ int   g_cand[(size_t)NROWS * CANDCAP];
__device__ uint4 g_Bimg4[8 * 4096];   // 8 chunks x 64KB swizzled bf16 B images

// ---------------------------------------------------------------------------
// PTX helpers — ALL base-sm_103-safe (sm_80-era instructions only)
__device__ __forceinline__ uint32_t s2u(const void* p) {
    uint32_t a;
    asm("{ .reg .u64 t; cvta.to.shared.u64 t, %1; cvt.u32.u64 %0, t; }"
        : "=r"(a) : "l"(p));
    return a;
}
#define LDSM4(r0, r1, r2, r3, addr) \
    asm volatile("ldmatrix.sync.aligned.m8n8.x4.shared.b16 {%0,%1,%2,%3}, [%4];" \
        : "=r"(r0), "=r"(r1), "=r"(r2), "=r"(r3) : "r"(addr))
#define MMA16816(d, a, b0, b1) \
    asm volatile("mma.sync.aligned.m16n8k16.row.col.f32.bf16.bf16.f32 " \
        "{%0,%1,%2,%3}, {%4,%5,%6,%7}, {%8,%9}, {%0,%1,%2,%3};" \
        : "+f"((d)[0]), "+f"((d)[1]), "+f"((d)[2]), "+f"((d)[3]) \
        : "r"((a)[0]), "r"((a)[1]), "r"((a)[2]), "r"((a)[3]), "r"(b0), "r"(b1))
#define CPASYNC16(dst, src) \
    asm volatile("cp.async.cg.shared.global [%0], [%1], 16;" :: "r"(dst), "l"(src))
#define CPCOMMIT() asm volatile("cp.async.commit_group;" ::: "memory")
#define CPWAIT1()  asm volatile("cp.async.wait_group 1;" ::: "memory")
#define CPWAIT0()  asm volatile("cp.async.wait_group 0;" ::: "memory")

// ---------------------------------------------------------------------------
// e_sq: sequential-c fp32 chain (identical to the round-2 winner)
__global__ void k_esq(const float* __restrict__ emb) {
    int k = blockIdx.x * blockDim.x + threadIdx.x;
    if (k < KCODES) {
        const float* row = emb + (size_t)k * CHAN;
        float acc = 0.0f;
        #pragma unroll 8
        for (int c = 0; c < CHAN; ++c) acc = fmaf(row[c], row[c], acc);
        g_esq[k] = acc;
    }
}

// z_sq: sequential-c fp32 chain, coalesced over rows
__global__ void k_zsq(const float* __restrict__ z) {
    int t = blockIdx.x;
    int b = t >> 3, hw0 = (t & 7) << 7;
    int r = threadIdx.x;
    const float* base = z + (size_t)b * CHAN * HWSZ + hw0 + r;
    float acc = 0.0f;
    #pragma unroll 8
    for (int c = 0; c < CHAN; ++c) {
        float v = base[(size_t)c * HWSZ];
        acc = fmaf(v, v, acc);
    }
    g_zsq[t * TILE_R + r] = acc;
}

// ---------------------------------------------------------------------------
// Pack codebook bf16 into swizzled per-chunk SMEM images (128 codes/chunk).
// Layout: code row 512B; 16B chunk index c16 swizzled by (code & 7).
__global__ void k_prep_emb(const float* __restrict__ emb) {
    int k  = blockIdx.x;            // code 0..1023
    int c  = threadIdx.x * 2;       // even channel
    float f0 = emb[(size_t)k * CHAN + c];
    float f1 = emb[(size_t)k * CHAN + c + 1];
    __nv_bfloat162 h2 = __floats2bfloat162_rn(f0, f1);   // x=low=c, y=high=c+1
    uint32_t u = *(uint32_t*)&h2;
    int chunk = k >> 7, cl = k & 127;
    int c16 = c >> 3;
    uint32_t addr = (uint32_t)cl * 512u
                  + (uint32_t)((c16 ^ (cl & 7)) << 4) + (uint32_t)(c & 7) * 2u;
    ((uint32_t*)g_Bimg4)[chunk * 16384 + (addr >> 2)] = u;
}

// ---------------------------------------------------------------------------
__device__ __forceinline__ void prefetch_chunk(uint32_t ab, int tid, int ch) {
    const char* src = (const char*)g_Bimg4 + (size_t)ch * 65536;
    uint32_t dst = ab + BBUF_OFF + (uint32_t)(ch & 1) * 65536u;
    #pragma unroll 4
    for (int i = tid; i < 4096; i += 256)
        CPASYNC16(dst + (uint32_t)i * 16u, src + (size_t)i * 16);
    CPCOMMIT();
}

// ---------------------------------------------------------------------------
// Main HMMA distance kernel: per CTA 128 rows x 1024 codes, K=256 bf16.
// 8 warps = 4(M) x 2(N); warp tile 32 x 64; mma m16n8k16.
__global__ void __launch_bounds__(256, 1)
k_main_mma(const float* __restrict__ z) {
    extern __shared__ char dsm[];
    uint32_t raw = s2u(dsm);
    uint32_t ab  = (raw + 1023u) & ~1023u;
    char* sm = dsm + (ab - raw);

    const int tid  = threadIdx.x;
    const int lane = tid & 31, w = tid >> 5;
    const int gid  = lane >> 2, tig = lane & 3;
    const int wm   = w >> 1,  wn = w & 1;
    const int t    = blockIdx.x;
    const int b    = t >> 3, hw0 = (t & 7) << 7;

    float* esq_s = (float*)(sm + ESQ_OFF);
    float* zsq_s = (float*)(sm + ZSQ_OFF);
    int*   cnt_s = (int*)(sm + CNT_OFF);
    int*   cand_s = (int*)(sm + CAND_OFF);

    for (int i = tid; i < KCODES; i += 256) esq_s[i] = g_esq[i];
    if (tid < 128) { zsq_s[tid] = g_zsq[t * 128 + tid]; cnt_s[tid] = 0; }

    // ---- Stage A: z -> bf16 swizzled [row][c], via f32 transpose scratch ----
    const float* zb = z + (size_t)b * CHAN * HWSZ + hw0;
    for (int h = 0; h < 2; ++h) {
        float* S = (float*)(sm + BBUF_OFF);    // [128 c][132] f32 scratch
        __syncthreads();
        for (int i = tid; i < 4096; i += 256) {
            int c = i >> 5, r4 = (i & 31) << 2;
            float4 v = *(const float4*)(zb + (size_t)(h * 128 + c) * HWSZ + r4);
            *(float4*)(S + c * 132 + r4) = v;
        }
        __syncthreads();
        int r = tid & 127, seg = tid >> 7;
        #pragma unroll
        for (int c8 = 0; c8 < 8; ++c8) {
            int cl = seg * 64 + c8 * 8;
            float f[8];
            #pragma unroll
            for (int j = 0; j < 8; ++j) f[j] = S[(cl + j) * 132 + r];
            uint32_t u[4];
            #pragma unroll
            for (int p = 0; p < 4; ++p) {
                __nv_bfloat162 h2 = __floats2bfloat162_rn(f[2*p], f[2*p+1]);
                u[p] = *(uint32_t*)&h2;
            }
            int cg = h * 128 + cl;
            uint32_t off = (uint32_t)r * 512u
                         + (uint32_t)(((cg >> 3) ^ (r & 7)) << 4);
            *(uint4*)(sm + A_OFF + off) = make_uint4(u[0], u[1], u[2], u[3]);
        }
    }
    __syncthreads();

    prefetch_chunk(ab, tid, 0);
    prefetch_chunk(ab, tid, 1);

    float zs[4];
    #pragma unroll
    for (int mt = 0; mt < 2; ++mt)
        #pragma unroll
        for (int hf = 0; hf < 2; ++hf)
            zs[mt * 2 + hf] = zsq_s[wm * 32 + mt * 16 + hf * 8 + gid];

    float rund[4] = {FLT_BIG, FLT_BIG, FLT_BIG, FLT_BIG};
    const uint32_t Abase = ab + A_OFF + (uint32_t)(wm * 32) * 512u;
    const int grp = lane >> 3, lr = lane & 7;

    for (int ch = 0; ch < 8; ++ch) {
        if (ch == 7) { CPWAIT0(); } else { CPWAIT1(); }
        __syncthreads();
        const uint32_t Bbase = ab + BBUF_OFF + (uint32_t)(ch & 1) * 65536u
                             + (uint32_t)(wn * 64) * 512u;
        float acc[2][8][4];
        #pragma unroll
        for (int mt = 0; mt < 2; ++mt)
            #pragma unroll
            for (int nt = 0; nt < 8; ++nt)
                #pragma unroll
                for (int q = 0; q < 4; ++q) acc[mt][nt][q] = 0.0f;

        #pragma unroll
        for (int kk = 0; kk < 16; ++kk) {
            uint32_t aR[2][4], bR[4][4];
            int ac16 = 2 * kk + (grp >> 1);
            int arow = (grp & 1) * 8 + lr;
            uint32_t axor = (uint32_t)((ac16 ^ lr) << 4);
            #pragma unroll
            for (int mt = 0; mt < 2; ++mt) {
                uint32_t addr = Abase + (uint32_t)(mt * 16 + arow) * 512u + axor;
                LDSM4(aR[mt][0], aR[mt][1], aR[mt][2], aR[mt][3], addr);
            }
            int bc16  = 2 * kk + (grp & 1);
            int bcode = (grp >> 1) * 8 + lr;
            uint32_t bxor = (uint32_t)((bc16 ^ lr) << 4);
            #pragma unroll
            for (int ntp = 0; ntp < 4; ++ntp) {
                uint32_t addr = Bbase + (uint32_t)(ntp * 16 + bcode) * 512u + bxor;
                LDSM4(bR[ntp][0], bR[ntp][1], bR[ntp][2], bR[ntp][3], addr);
            }
            #pragma unroll
            for (int mt = 0; mt < 2; ++mt)
                #pragma unroll
                for (int nt = 0; nt < 8; ++nt)
                    MMA16816(acc[mt][nt], aR[mt],
                             bR[nt >> 1][(nt & 1) * 2],
                             bR[nt >> 1][(nt & 1) * 2 + 1]);
        }

        // ---- chunk epilogue: running row-min + candidate capture ----
        float es[16];
        #pragma unroll
        for (int nt = 0; nt < 8; ++nt)
            #pragma unroll
            for (int c01 = 0; c01 < 2; ++c01)
                es[nt * 2 + c01] = esq_s[ch * 128 + wn * 64 + nt * 8 + 2 * tig + c01];

        #pragma unroll
        for (int mt = 0; mt < 2; ++mt)
            #pragma unroll
            for (int hf = 0; hf < 2; ++hf) {
                int slot = mt * 2 + hf;
                float mn = FLT_BIG;
                #pragma unroll
                for (int nt = 0; nt < 8; ++nt)
                    #pragma unroll
                    for (int c01 = 0; c01 < 2; ++c01) {
                        float d = fmaf(-2.0f, acc[mt][nt][hf * 2 + c01],
                                       zs[slot] + es[nt * 2 + c01]);
                        if (d < mn) mn = d;
                    }
                #pragma unroll
                for (int o = 1; o <= 2; o <<= 1)
                    mn = fminf(mn, __shfl_xor_sync(0xFFFFFFFFu, mn, o));
                if (mn < rund[slot]) rund[slot] = mn;
                float thr = rund[slot] + EPS_CAND;
                int rloc = wm * 32 + mt * 16 + hf * 8 + gid;
                #pragma unroll
                for (int nt = 0; nt < 8; ++nt)
                    #pragma unroll
                    for (int c01 = 0; c01 < 2; ++c01) {
                        float d = fmaf(-2.0f, acc[mt][nt][hf * 2 + c01],
                                       zs[slot] + es[nt * 2 + c01]);
                        if (d <= thr) {
                            int pos = atomicAdd(&cnt_s[rloc], 1);
                            if (pos < CANDCAP)
                                cand_s[rloc * CANDCAP + pos] =
                                    ch * 128 + wn * 64 + nt * 8 + 2 * tig + c01;
                        }
                    }
            }
        __syncthreads();
        if (ch < 6) prefetch_chunk(ab, tid, ch + 2);
    }
    __syncthreads();
    if (tid < 128) g_cnt[t * 128 + tid] = cnt_s[tid];
    for (int i = tid; i < 128 * CANDCAP; i += 256)
        g_cand[(size_t)(t * 128) * CANDCAP + i] = cand_s[i];
}

// ---------------------------------------------------------------------------
// Exact refine: recompute candidates with the exact sequential fp32 chain;
// lexicographic (d, k) min == first-occurrence argmin (round-2 semantics).
__device__ __forceinline__ float exact_d(const float* __restrict__ zp,
                                         const float* __restrict__ ep,
                                         float zsv, float esk) {
    float acc = 0.0f;
    #pragma unroll 8
    for (int c = 0; c < CHAN; ++c)
        acc = fmaf(zp[(size_t)c << 10], ep[c], acc);
    return __fmaf_rn(-2.0f, acc, zsv + esk);
}

__global__ void k_refine(const float* __restrict__ z, const float* __restrict__ emb) {
    int tid = threadIdx.x, lid = tid & 31;
    int n = blockIdx.x * 8 + (tid >> 5);
    int b = n >> 10, hw = n & 1023;
    const float* zp = z + (size_t)b * CHAN * HWSZ + hw;
    float zsv = g_zsq[n];
    int cnt = g_cnt[n];

    float d = FLT_BIG;
    int bk = 1 << 30;
    if (cnt <= CANDCAP) {
        if (lid < cnt) {
            int k = g_cand[(size_t)n * CANDCAP + lid];
            d = exact_d(zp, emb + (size_t)k * CHAN, zsv, g_esq[k]);
            bk = k;
        }
    } else {
        for (int k = lid; k < KCODES; k += 32) {
            float dd = exact_d(zp, emb + (size_t)k * CHAN, zsv, g_esq[k]);
            if (dd < d) { d = dd; bk = k; }
        }
    }
    #pragma unroll
    for (int o = 16; o; o >>= 1) {
        float od = __shfl_down_sync(0xFFFFFFFFu, d, o);
        int   ok = __shfl_down_sync(0xFFFFFFFFu, bk, o);
        if (od < d || (od == d && ok < bk)) { d = od; bk = ok; }
    }
    if (lid == 0) g_idx[n] = bk;
}

// ---------------------------------------------------------------------------
// Output + loss partials: smem-staged gather, 64-channel groups.
__global__ void k_out(const float* __restrict__ z, const float* __restrict__ emb,
                      float* __restrict__ out) {
    __shared__ int   sidx[TILE_R];
    __shared__ float qs[TILE_R][69];
    __shared__ float red[256];

    int t = blockIdx.x, cg = blockIdx.y;
    int b = t >> 3, hw0 = (t & 7) << 7;
    int tid = threadIdx.x;

    if (tid < TILE_R) sidx[tid] = g_idx[t * TILE_R + tid];
    __syncthreads();

    {
        int row = tid >> 1, half = tid & 1;
        const float4* e4 = (const float4*)(emb + (size_t)sidx[row] * CHAN + cg * 64);
        #pragma unroll
        for (int q = 0; q < 8; ++q) {
            float4 v = e4[half * 8 + q];
            int c0 = half * 32 + q * 4;
            qs[row][c0] = v.x; qs[row][c0 + 1] = v.y;
            qs[row][c0 + 2] = v.z; qs[row][c0 + 3] = v.w;
        }
    }
    __syncthreads();

    float acc = 0.0f;
    int r = tid & 127, chp = tid >> 7;
    #pragma unroll
    for (int p = 0; p < 32; ++p) {
        int c = cg * 64 + p * 2 + chp;
        size_t off = ((size_t)(b * CHAN + c)) * HWSZ + hw0 + r;
        float q  = qs[r][p * 2 + chp];
        float zv = z[off];
        out[off] = q;
        float df = q - zv;
        acc = fmaf(df, df, acc);
    }
    red[tid] = acc;
    __syncthreads();
    #pragma unroll
    for (int s = 128; s > 0; s >>= 1) {
        if (tid < s) red[tid] += red[tid + s];
        __syncthreads();
    }
    if (tid == 0) g_part[t * 4 + cg] = red[0];
}

__global__ void k_final(float* __restrict__ out) {
    __shared__ float red[256];
    int tid = threadIdx.x;
    float a = 0.0f;
    for (int i = tid; i < NPART; i += 256) a += g_part[i];
    red[tid] = a;
    __syncthreads();
    #pragma unroll
    for (int s = 128; s > 0; s >>= 1) {
        if (tid < s) red[tid] += red[tid + s];
        __syncthreads();
    }
    if (tid == 0) out[16777216] = 1.25f * (red[0] / 16777216.0f);
}

// ---------------------------------------------------------------------------
extern "C" void kernel_launch(void* const* d_in, const int* in_sizes, int n_in,
                              void* d_out, int out_size) {
    const float* z   = (const float*)d_in[0];   // [64,256,32,32]
    const float* emb = (const float*)d_in[1];   // [1024,256]
    float* out = (float*)d_out;

    cudaFuncSetAttribute(k_main_mma, cudaFuncAttributeMaxDynamicSharedMemorySize,
                         SMEM_REQ);

    k_esq<<<8, 128>>>(emb);
    k_zsq<<<NTILES, 128>>>(z);
    k_prep_emb<<<KCODES, 128>>>(emb);
    k_main_mma<<<NTILES, 256, SMEM_REQ>>>(z);
    k_refine<<<NROWS / 8, 256>>>(z, emb);
    dim3 g(NTILES, 4);
    k_out<<<g, 256>>>(z, emb, out);
    k_final<<<1, 256>>>(out);
}

// round 8
// speedup vs baseline: 1.9387x; 1.2881x over previous
#include <cuda_runtime.h>
#include <cuda_bf16.h>
#include <cstdint>

// ---------------------------------------------------------------------------
// Problem constants
#define BATCH   64
#define CHAN    256
#define HWSZ    1024
#define NROWS   65536
#define KCODES  1024
#define TILE_R  128
#define NTILES  512
#define NPART   2048
#define EPS_CAND 4e-3f
#define CANDCAP  16
#define FLT_BIG  3.4028235e38f

// SMEM layout for k_main (relative to 1024-aligned base)
#define A_OFF    0          // 128 rows x 256 c bf16, swizzled: 65536 B
#define BBUF_OFF 65536      // two B buffers, 65536 B each (also A-stage scratch)
#define ESQ_OFF  196608     // 1024 f32
#define ZSQ_OFF  200704     // 128 f32
#define CNT_OFF  201216     // 128 int
#define ROWB_OFF 201728     // 128 int (float-as-int running row min)
#define CAND_OFF 202240     // 128*16 int = 8192 B
#define SMEM_END 210432
#define SMEM_REQ (SMEM_END + 1024)

// ---------------------------------------------------------------------------
// Scratch (static device globals; no runtime allocation)
__device__ float g_esq[KCODES];
__device__ float g_zsq[NROWS];
__device__ int   g_idx[NROWS];
__device__ int   g_cnt[NROWS];
__device__ float g_part[NPART];
__device__ int   g_cand[(size_t)NROWS * CANDCAP];
__device__ uint4 g_Bimg4[8 * 4096];            // 8 chunks x 64KB swizzled B
__device__ float g_zt[(size_t)NROWS * CHAN];   // transposed z [n][c], 64MB

// ---------------------------------------------------------------------------
// PTX helpers — base-sm_103-safe (sm_80-era instructions only)
__device__ __forceinline__ uint32_t s2u(const void* p) {
    uint32_t a;
    asm("{ .reg .u64 t; cvta.to.shared.u64 t, %1; cvt.u32.u64 %0, t; }"
        : "=r"(a) : "l"(p));
    return a;
}
#define LDSM4(r0, r1, r2, r3, addr) \
    asm volatile("ldmatrix.sync.aligned.m8n8.x4.shared.b16 {%0,%1,%2,%3}, [%4];" \
        : "=r"(r0), "=r"(r1), "=r"(r2), "=r"(r3) : "r"(addr))
#define MMA16816(d, a, b0, b1) \
    asm volatile("mma.sync.aligned.m16n8k16.row.col.f32.bf16.bf16.f32 " \
        "{%0,%1,%2,%3}, {%4,%5,%6,%7}, {%8,%9}, {%0,%1,%2,%3};" \
        : "+f"((d)[0]), "+f"((d)[1]), "+f"((d)[2]), "+f"((d)[3]) \
        : "r"((a)[0]), "r"((a)[1]), "r"((a)[2]), "r"((a)[3]), "r"(b0), "r"(b1))
#define CPASYNC16(dst, src) \
    asm volatile("cp.async.cg.shared.global [%0], [%1], 16;" :: "r"(dst), "l"(src))
#define CPCOMMIT() asm volatile("cp.async.commit_group;" ::: "memory")
#define CPWAIT1()  asm volatile("cp.async.wait_group 1;" ::: "memory")
#define CPWAIT0()  asm volatile("cp.async.wait_group 0;" ::: "memory")

// ---------------------------------------------------------------------------
// e_sq: sequential-c fp32 chain (unchanged from passing rounds)
__global__ void k_esq(const float* __restrict__ emb) {
    int k = blockIdx.x * blockDim.x + threadIdx.x;
    if (k < KCODES) {
        const float* row = emb + (size_t)k * CHAN;
        float acc = 0.0f;
        #pragma unroll 8
        for (int c = 0; c < CHAN; ++c) acc = fmaf(row[c], row[c], acc);
        g_esq[k] = acc;
    }
}

// z_sq: sequential-c fp32 chain (unchanged — preserves selection semantics)
__global__ void k_zsq(const float* __restrict__ z) {
    int t = blockIdx.x;
    int b = t >> 3, hw0 = (t & 7) << 7;
    int r = threadIdx.x;
    const float* base = z + (size_t)b * CHAN * HWSZ + hw0 + r;
    float acc = 0.0f;
    #pragma unroll 8
    for (int c = 0; c < CHAN; ++c) {
        float v = base[(size_t)c * HWSZ];
        acc = fmaf(v, v, acc);
    }
    g_zsq[t * TILE_R + r] = acc;
}

// ---------------------------------------------------------------------------
// Transpose z -> z_t[n][c] (row-contiguous) for coalesced refine loads.
__global__ void k_zt(const float* __restrict__ z) {
    __shared__ float S[32 * 132];
    int t = blockIdx.x;
    int b = t >> 3, hw0 = (t & 7) << 7;
    int tid = threadIdx.x;
    const float* zb = z + (size_t)b * CHAN * HWSZ + hw0;

    for (int g = 0; g < 8; ++g) {
        #pragma unroll
        for (int it = 0; it < 4; ++it) {
            int cl = it * 8 + (tid >> 5);
            int r4 = (tid & 31) << 2;
            float4 v = *(const float4*)(zb + (size_t)(g * 32 + cl) * HWSZ + r4);
            *(float4*)(S + cl * 132 + r4) = v;
        }
        __syncthreads();
        int r = tid >> 1, half = tid & 1;
        float* dst = g_zt + ((size_t)(t * TILE_R + r)) * CHAN + g * 32 + half * 16;
        #pragma unroll
        for (int q = 0; q < 4; ++q) {
            int c0 = half * 16 + q * 4;
            float4 v;
            v.x = S[(c0 + 0) * 132 + r];
            v.y = S[(c0 + 1) * 132 + r];
            v.z = S[(c0 + 2) * 132 + r];
            v.w = S[(c0 + 3) * 132 + r];
            *(float4*)(dst + q * 4) = v;
        }
        __syncthreads();
    }
}

// ---------------------------------------------------------------------------
// Pack codebook bf16 into swizzled per-chunk SMEM images (128 codes/chunk).
__global__ void k_prep_emb(const float* __restrict__ emb) {
    int k  = blockIdx.x;
    int c  = threadIdx.x * 2;
    float f0 = emb[(size_t)k * CHAN + c];
    float f1 = emb[(size_t)k * CHAN + c + 1];
    __nv_bfloat162 h2 = __floats2bfloat162_rn(f0, f1);
    uint32_t u = *(uint32_t*)&h2;
    int chunk = k >> 7, cl = k & 127;
    int c16 = c >> 3;
    uint32_t addr = (uint32_t)cl * 512u
                  + (uint32_t)((c16 ^ (cl & 7)) << 4) + (uint32_t)(c & 7) * 2u;
    ((uint32_t*)g_Bimg4)[chunk * 16384 + (addr >> 2)] = u;
}

// ---------------------------------------------------------------------------
__device__ __forceinline__ void prefetch_chunk(uint32_t ab, int tid, int ch) {
    const char* src = (const char*)g_Bimg4 + (size_t)ch * 65536;
    uint32_t dst = ab + BBUF_OFF + (uint32_t)(ch & 1) * 65536u;
    #pragma unroll 2
    for (int i = tid; i < 4096; i += 512)
        CPASYNC16(dst + (uint32_t)i * 16u, src + (size_t)i * 16);
    CPCOMMIT();
}

// ---------------------------------------------------------------------------
// Main HMMA distance kernel: 512 threads = 16 warps (4M x 4N), warp 32x32.
__global__ void __launch_bounds__(512, 1)
k_main_mma(const float* __restrict__ z) {
    extern __shared__ char dsm[];
    uint32_t raw = s2u(dsm);
    uint32_t ab  = (raw + 1023u) & ~1023u;
    char* sm = dsm + (ab - raw);

    const int tid  = threadIdx.x;
    const int lane = tid & 31, w = tid >> 5;
    const int gid  = lane >> 2, tig = lane & 3;
    const int wm   = w >> 2,  wn = w & 3;
    const int t    = blockIdx.x;
    const int b    = t >> 3, hw0 = (t & 7) << 7;

    float* esq_s = (float*)(sm + ESQ_OFF);
    float* zsq_s = (float*)(sm + ZSQ_OFF);
    int*   cnt_s = (int*)(sm + CNT_OFF);
    int*   rb_s  = (int*)(sm + ROWB_OFF);
    int*   cand_s = (int*)(sm + CAND_OFF);

    for (int i = tid; i < KCODES; i += 512) esq_s[i] = g_esq[i];
    if (tid < 128) {
        zsq_s[tid] = g_zsq[t * 128 + tid];
        cnt_s[tid] = 0;
        rb_s[tid]  = 0x7F7FFFFF;      // +FLT_MAX as int
    }

    // ---- Stage A: z -> bf16 swizzled [row][c], via f32 transpose scratch ----
    const float* zb = z + (size_t)b * CHAN * HWSZ + hw0;
    for (int h = 0; h < 2; ++h) {
        float* S = (float*)(sm + BBUF_OFF);    // [128 c][132] f32 scratch
        __syncthreads();
        for (int i = tid; i < 4096; i += 512) {
            int c = i >> 5, r4 = (i & 31) << 2;
            float4 v = *(const float4*)(zb + (size_t)(h * 128 + c) * HWSZ + r4);
            *(float4*)(S + c * 132 + r4) = v;
        }
        __syncthreads();
        int r = tid & 127, seg = tid >> 7;     // seg 0..3
        #pragma unroll
        for (int c8 = 0; c8 < 4; ++c8) {
            int cl = seg * 32 + c8 * 8;
            float f[8];
            #pragma unroll
            for (int j = 0; j < 8; ++j) f[j] = S[(cl + j) * 132 + r];
            uint32_t u[4];
            #pragma unroll
            for (int p = 0; p < 4; ++p) {
                __nv_bfloat162 h2 = __floats2bfloat162_rn(f[2*p], f[2*p+1]);
                u[p] = *(uint32_t*)&h2;
            }
            int cg = h * 128 + cl;
            uint32_t off = (uint32_t)r * 512u
                         + (uint32_t)(((cg >> 3) ^ (r & 7)) << 4);
            *(uint4*)(sm + A_OFF + off) = make_uint4(u[0], u[1], u[2], u[3]);
        }
    }
    __syncthreads();

    prefetch_chunk(ab, tid, 0);
    prefetch_chunk(ab, tid, 1);

    float zs[4];
    #pragma unroll
    for (int mt = 0; mt < 2; ++mt)
        #pragma unroll
        for (int hf = 0; hf < 2; ++hf)
            zs[mt * 2 + hf] = zsq_s[wm * 32 + mt * 16 + hf * 8 + gid];

    const uint32_t Abase = ab + A_OFF + (uint32_t)(wm * 32) * 512u;
    const int grp = lane >> 3, lr = lane & 7;

    for (int ch = 0; ch < 8; ++ch) {
        if (ch == 7) { CPWAIT0(); } else { CPWAIT1(); }
        __syncthreads();
        const uint32_t Bbase = ab + BBUF_OFF + (uint32_t)(ch & 1) * 65536u
                             + (uint32_t)(wn * 32) * 512u;
        float acc[2][4][4];
        #pragma unroll
        for (int mt = 0; mt < 2; ++mt)
            #pragma unroll
            for (int nt = 0; nt < 4; ++nt)
                #pragma unroll
                for (int q = 0; q < 4; ++q) acc[mt][nt][q] = 0.0f;

        #pragma unroll
        for (int kk = 0; kk < 16; ++kk) {
            uint32_t aR[2][4], bR[2][4];
            int ac16 = 2 * kk + (grp >> 1);
            int arow = (grp & 1) * 8 + lr;
            uint32_t axor = (uint32_t)((ac16 ^ lr) << 4);
            #pragma unroll
            for (int mt = 0; mt < 2; ++mt) {
                uint32_t addr = Abase + (uint32_t)(mt * 16 + arow) * 512u + axor;
                LDSM4(aR[mt][0], aR[mt][1], aR[mt][2], aR[mt][3], addr);
            }
            int bc16  = 2 * kk + (grp & 1);
            int bcode = (grp >> 1) * 8 + lr;
            uint32_t bxor = (uint32_t)((bc16 ^ lr) << 4);
            #pragma unroll
            for (int ntp = 0; ntp < 2; ++ntp) {
                uint32_t addr = Bbase + (uint32_t)(ntp * 16 + bcode) * 512u + bxor;
                LDSM4(bR[ntp][0], bR[ntp][1], bR[ntp][2], bR[ntp][3], addr);
            }
            #pragma unroll
            for (int mt = 0; mt < 2; ++mt)
                #pragma unroll
                for (int nt = 0; nt < 4; ++nt)
                    MMA16816(acc[mt][nt], aR[mt],
                             bR[nt >> 1][(nt & 1) * 2],
                             bR[nt >> 1][(nt & 1) * 2 + 1]);
        }

        // ---- epilogue: global per-row running min, then candidate capture ----
        float es[8];
        #pragma unroll
        for (int nt = 0; nt < 4; ++nt)
            #pragma unroll
            for (int c01 = 0; c01 < 2; ++c01)
                es[nt * 2 + c01] = esq_s[ch * 128 + wn * 32 + nt * 8 + 2 * tig + c01];

        #pragma unroll
        for (int mt = 0; mt < 2; ++mt)
            #pragma unroll
            for (int hf = 0; hf < 2; ++hf) {
                int slot = mt * 2 + hf;
                float mn = FLT_BIG;
                #pragma unroll
                for (int nt = 0; nt < 4; ++nt)
                    #pragma unroll
                    for (int c01 = 0; c01 < 2; ++c01) {
                        float d = fmaf(-2.0f, acc[mt][nt][hf * 2 + c01],
                                       zs[slot] + es[nt * 2 + c01]);
                        if (d < mn) mn = d;
                    }
                #pragma unroll
                for (int o = 1; o <= 2; o <<= 1)
                    mn = fminf(mn, __shfl_xor_sync(0xFFFFFFFFu, mn, o));
                if (tig == 0) {
                    int rloc = wm * 32 + mt * 16 + hf * 8 + gid;
                    atomicMin(&rb_s[rloc], __float_as_int(mn));  // d > 0 always
                }
            }
        __syncthreads();

        #pragma unroll
        for (int mt = 0; mt < 2; ++mt)
            #pragma unroll
            for (int hf = 0; hf < 2; ++hf) {
                int slot = mt * 2 + hf;
                int rloc = wm * 32 + mt * 16 + hf * 8 + gid;
                float thr = __int_as_float(rb_s[rloc]) + EPS_CAND;
                #pragma unroll
                for (int nt = 0; nt < 4; ++nt)
                    #pragma unroll
                    for (int c01 = 0; c01 < 2; ++c01) {
                        float d = fmaf(-2.0f, acc[mt][nt][hf * 2 + c01],
                                       zs[slot] + es[nt * 2 + c01]);
                        if (d <= thr) {
                            int pos = atomicAdd(&cnt_s[rloc], 1);
                            if (pos < CANDCAP)
                                cand_s[rloc * CANDCAP + pos] =
                                    ch * 128 + wn * 32 + nt * 8 + 2 * tig + c01;
                        }
                    }
            }
        __syncthreads();
        if (ch < 6) prefetch_chunk(ab, tid, ch + 2);
    }
    __syncthreads();
    if (tid < 128) g_cnt[t * 128 + tid] = cnt_s[tid];
    for (int i = tid; i < 128 * CANDCAP; i += 512)
        g_cand[(size_t)(t * 128) * CANDCAP + i] = cand_s[i];
}

// ---------------------------------------------------------------------------
// Refine: warp per row, lane per candidate. Dot is the EXACT sequential fp32
// chain over ascending c (bit-identical to the round-2/6 verified selection);
// z row comes from SMEM (staged from contiguous z_t), emb rows are L1-hot.
// Lexicographic (d, k) min == first-occurrence argmin.
__global__ void __launch_bounds__(256, 4)
k_refine(const float* __restrict__ emb) {
    __shared__ float zs[8][CHAN];
    int tid = threadIdx.x, lid = tid & 31, wrp = tid >> 5;
    int n = blockIdx.x * 8 + wrp;

    {   // stage z row (coalesced: 64 float4 per warp)
        const float4* zr4 = (const float4*)(g_zt + (size_t)n * CHAN);
        float4* zd4 = (float4*)zs[wrp];
        zd4[lid]      = zr4[lid];
        zd4[lid + 32] = zr4[lid + 32];
    }
    __syncwarp();

    float zsv = g_zsq[n];
    int cnt = g_cnt[n];
    const float* zrow = zs[wrp];

    float bd = FLT_BIG;
    int bk = 1 << 30;

    if (cnt <= CANDCAP) {
        if (lid < cnt) {
            int k = g_cand[(size_t)n * CANDCAP + lid];
            const float* ep = emb + (size_t)k * CHAN;
            float acc = 0.0f;
            #pragma unroll 8
            for (int c = 0; c < CHAN; ++c)
                acc = fmaf(zrow[c], ep[c], acc);
            bd = __fmaf_rn(-2.0f, acc, zsv + g_esq[k]);
            bk = k;
        }
    } else {
        for (int k = lid; k < KCODES; k += 32) {
            const float* ep = emb + (size_t)k * CHAN;
            float acc = 0.0f;
            #pragma unroll 8
            for (int c = 0; c < CHAN; ++c)
                acc = fmaf(zrow[c], ep[c], acc);
            float d = __fmaf_rn(-2.0f, acc, zsv + g_esq[k]);
            if (d < bd || (d == bd && k < bk)) { bd = d; bk = k; }
        }
    }
    #pragma unroll
    for (int o = 16; o; o >>= 1) {
        float od = __shfl_down_sync(0xFFFFFFFFu, bd, o);
        int   ok = __shfl_down_sync(0xFFFFFFFFu, bk, o);
        if (od < bd || (od == bd && ok < bk)) { bd = od; bk = ok; }
    }
    if (lid == 0) g_idx[n] = bk;
}

// ---------------------------------------------------------------------------
// Output + loss partials. Mimic the reference straight-through arithmetic:
// out = z + (q - z)  (NOT the raw gather), loss term df^2 with df = q - z.
__global__ void k_out(const float* __restrict__ z, const float* __restrict__ emb,
                      float* __restrict__ out) {
    __shared__ int   sidx[TILE_R];
    __shared__ float qs[TILE_R][69];
    __shared__ float red[256];

    int t = blockIdx.x, cg = blockIdx.y;
    int b = t >> 3, hw0 = (t & 7) << 7;
    int tid = threadIdx.x;

    if (tid < TILE_R) sidx[tid] = g_idx[t * TILE_R + tid];
    __syncthreads();

    {
        int row = tid >> 1, half = tid & 1;
        const float4* e4 = (const float4*)(emb + (size_t)sidx[row] * CHAN + cg * 64);
        #pragma unroll
        for (int q = 0; q < 8; ++q) {
            float4 v = e4[half * 8 + q];
            int c0 = half * 32 + q * 4;
            qs[row][c0] = v.x; qs[row][c0 + 1] = v.y;
            qs[row][c0 + 2] = v.z; qs[row][c0 + 3] = v.w;
        }
    }
    __syncthreads();

    float acc = 0.0f;
    int r = tid & 127, chp = tid >> 7;
    #pragma unroll
    for (int p = 0; p < 32; ++p) {
        int c = cg * 64 + p * 2 + chp;
        size_t off = ((size_t)(b * CHAN + c)) * HWSZ + hw0 + r;
        float q  = qs[r][p * 2 + chp];
        float zv = z[off];
        float df = q - zv;
        out[off] = zv + df;                 // straight-through rounding mimic
        acc = fmaf(df, df, acc);
    }
    red[tid] = acc;
    __syncthreads();
    #pragma unroll
    for (int s = 128; s > 0; s >>= 1) {
        if (tid < s) red[tid] += red[tid + s];
        __syncthreads();
    }
    if (tid == 0) g_part[t * 4 + cg] = red[0];
}

// loss = m + 0.25*m, m = mean(df^2); fixed-order deterministic reduction.
__global__ void k_final(float* __restrict__ out) {
    __shared__ float red[256];
    int tid = threadIdx.x;
    float a = 0.0f;
    for (int i = tid; i < NPART; i += 256) a += g_part[i];
    red[tid] = a;
    __syncthreads();
    #pragma unroll
    for (int s = 128; s > 0; s >>= 1) {
        if (tid < s) red[tid] += red[tid + s];
        __syncthreads();
    }
    if (tid == 0) {
        float m = red[0] / 16777216.0f;
        out[16777216] = m + 0.25f * m;
    }
}

// ---------------------------------------------------------------------------
extern "C" void kernel_launch(void* const* d_in, const int* in_sizes, int n_in,
                              void* d_out, int out_size) {
    const float* z   = (const float*)d_in[0];   // [64,256,32,32]
    const float* emb = (const float*)d_in[1];   // [1024,256]
    float* out = (float*)d_out;

    cudaFuncSetAttribute(k_main_mma, cudaFuncAttributeMaxDynamicSharedMemorySize,
                         SMEM_REQ);

    k_esq<<<8, 128>>>(emb);
    k_zsq<<<NTILES, 128>>>(z);
    k_zt<<<NTILES, 256>>>(z);
    k_prep_emb<<<KCODES, 128>>>(emb);
    k_main_mma<<<NTILES, 512, SMEM_REQ>>>(z);
    k_refine<<<NROWS / 8, 256>>>(emb);
    dim3 g(NTILES, 4);
    k_out<<<g, 256>>>(z, emb, out);
    k_final<<<1, 256>>>(out);
}

// round 12
// speedup vs baseline: 1.9546x; 1.0082x over previous
#include <cuda_runtime.h>
#include <cuda_bf16.h>
#include <cstdint>

// ---------------------------------------------------------------------------
// Problem constants
#define BATCH   64
#define CHAN    256
#define HWSZ    1024
#define NROWS   65536
#define KCODES  1024
#define TILE_R  128
#define NTILES  512
#define NPART   2048
#define EPS_CAND 4e-3f
#define CANDCAP  16
#define FLT_BIG  3.4028235e38f

// SMEM layout for k_main (relative to 1024-aligned base)
#define A_OFF    0          // 128 rows x 256 c bf16, swizzled: 65536 B
#define BBUF_OFF 65536      // two B buffers, 65536 B each
#define ESQ_OFF  196608     // 1024 f32
#define ZSQ_OFF  200704     // 128 f32
#define CNT_OFF  201216     // 128 int
#define ROWB_OFF 201728     // 128 int (float-as-int running row min)
#define CAND_OFF 202240     // 128*16 int = 8192 B
#define SMEM_END 210432
#define SMEM_REQ (SMEM_END + 1024)

// ---------------------------------------------------------------------------
// Scratch (static device globals; no runtime allocation)
__device__ float g_esq[KCODES];
__device__ float g_zsq[NROWS];
__device__ int   g_idx[NROWS];
__device__ int   g_cnt[NROWS];
__device__ float g_part[NPART];
__device__ int   g_cand[(size_t)NROWS * CANDCAP];
__device__ uint4 g_Bimg4[8 * 4096];            // 8 chunks x 64KB swizzled B
__device__ uint4 g_Aimg4[NTILES * 4096];       // per-tile 64KB swizzled A, 32MB
__device__ float g_zt[(size_t)NROWS * CHAN];   // transposed z [n][c], 64MB

// ---------------------------------------------------------------------------
// PTX helpers — base-sm_103-safe (sm_80-era instructions only)
__device__ __forceinline__ uint32_t s2u(const void* p) {
    uint32_t a;
    asm("{ .reg .u64 t; cvta.to.shared.u64 t, %1; cvt.u32.u64 %0, t; }"
        : "=r"(a) : "l"(p));
    return a;
}
#define LDSM4(r0, r1, r2, r3, addr) \
    asm volatile("ldmatrix.sync.aligned.m8n8.x4.shared.b16 {%0,%1,%2,%3}, [%4];" \
        : "=r"(r0), "=r"(r1), "=r"(r2), "=r"(r3) : "r"(addr))
#define MMA16816(d, a, b0, b1) \
    asm volatile("mma.sync.aligned.m16n8k16.row.col.f32.bf16.bf16.f32 " \
        "{%0,%1,%2,%3}, {%4,%5,%6,%7}, {%8,%9}, {%0,%1,%2,%3};" \
        : "+f"((d)[0]), "+f"((d)[1]), "+f"((d)[2]), "+f"((d)[3]) \
        : "r"((a)[0]), "r"((a)[1]), "r"((a)[2]), "r"((a)[3]), "r"(b0), "r"(b1))
#define CPASYNC16(dst, src) \
    asm volatile("cp.async.cg.shared.global [%0], [%1], 16;" :: "r"(dst), "l"(src))
#define CPCOMMIT() asm volatile("cp.async.commit_group;" ::: "memory")
#define CPWAIT1()  asm volatile("cp.async.wait_group 1;" ::: "memory")
#define CPWAIT0()  asm volatile("cp.async.wait_group 0;" ::: "memory")

// ---------------------------------------------------------------------------
// Codebook prep: pack bf16 swizzled B images + e_sq sequential chain.
__global__ void k_embprep(const float* __restrict__ emb) {
    int k  = blockIdx.x;
    int c  = threadIdx.x * 2;
    float f0 = emb[(size_t)k * CHAN + c];
    float f1 = emb[(size_t)k * CHAN + c + 1];
    __nv_bfloat162 h2 = __floats2bfloat162_rn(f0, f1);
    uint32_t u = *(uint32_t*)&h2;
    int chunk = k >> 7, cl = k & 127;
    int c16 = c >> 3;
    uint32_t addr = (uint32_t)cl * 512u
                  + (uint32_t)((c16 ^ (cl & 7)) << 4) + (uint32_t)(c & 7) * 2u;
    ((uint32_t*)g_Bimg4)[chunk * 16384 + (addr >> 2)] = u;

    if (threadIdx.x == 0) {      // exact sequential-c fp32 chain (verified)
        const float* row = emb + (size_t)k * CHAN;
        float acc = 0.0f;
        #pragma unroll 8
        for (int cc = 0; cc < CHAN; ++cc) acc = fmaf(row[cc], row[cc], acc);
        g_esq[k] = acc;
    }
}

// ---------------------------------------------------------------------------
// z prep: transpose z -> z_t[n][c]; then z_sq (exact chain, same values/order
// as the verified kernel) and the swizzled bf16 A-image, both from z_t.
__global__ void k_zprep(const float* __restrict__ z) {
    __shared__ float S[32 * 132];
    int t = blockIdx.x;
    int b = t >> 3, hw0 = (t & 7) << 7;
    int tid = threadIdx.x;
    const float* zb = z + (size_t)b * CHAN * HWSZ + hw0;

    // Phase 1: transpose to g_zt
    for (int g = 0; g < 8; ++g) {
        #pragma unroll
        for (int it = 0; it < 4; ++it) {
            int cl = it * 8 + (tid >> 5);
            int r4 = (tid & 31) << 2;
            float4 v = *(const float4*)(zb + (size_t)(g * 32 + cl) * HWSZ + r4);
            *(float4*)(S + cl * 132 + r4) = v;
        }
        __syncthreads();
        int r = tid >> 1, half = tid & 1;
        float* dst = g_zt + ((size_t)(t * TILE_R + r)) * CHAN + g * 32 + half * 16;
        #pragma unroll
        for (int q = 0; q < 4; ++q) {
            int c0 = half * 16 + q * 4;
            float4 v;
            v.x = S[(c0 + 0) * 132 + r];
            v.y = S[(c0 + 1) * 132 + r];
            v.z = S[(c0 + 2) * 132 + r];
            v.w = S[(c0 + 3) * 132 + r];
            *(float4*)(dst + q * 4) = v;
        }
        __syncthreads();
    }

    // Phase 2a: z_sq — exact sequential fp32 chain over ascending c
    if (tid < TILE_R) {
        const float* zr = g_zt + (size_t)(t * TILE_R + tid) * CHAN;
        float acc = 0.0f;
        #pragma unroll 8
        for (int c = 0; c < CHAN; ++c) acc = fmaf(zr[c], zr[c], acc);
        g_zsq[t * TILE_R + tid] = acc;
    }

    // Phase 2b: bf16 swizzled A-image (64KB per tile) to global
    #pragma unroll
    for (int i = 0; i < 16; ++i) {
        int j = tid + i * 256;              // 0..4095
        int row = j >> 5, c16 = j & 31;
        const float4* zr4 = (const float4*)(g_zt
            + (size_t)(t * TILE_R + row) * CHAN + c16 * 8);
        float4 a = zr4[0], c = zr4[1];
        uint32_t u[4];
        __nv_bfloat162 h0 = __floats2bfloat162_rn(a.x, a.y); u[0] = *(uint32_t*)&h0;
        __nv_bfloat162 h1 = __floats2bfloat162_rn(a.z, a.w); u[1] = *(uint32_t*)&h1;
        __nv_bfloat162 h2 = __floats2bfloat162_rn(c.x, c.y); u[2] = *(uint32_t*)&h2;
        __nv_bfloat162 h3 = __floats2bfloat162_rn(c.z, c.w); u[3] = *(uint32_t*)&h3;
        uint32_t off = (uint32_t)row * 512u
                     + (uint32_t)((c16 ^ (row & 7)) << 4);
        g_Aimg4[(size_t)t * 4096 + (off >> 4)] = make_uint4(u[0], u[1], u[2], u[3]);
    }
}

// ---------------------------------------------------------------------------
__device__ __forceinline__ void prefetch_chunk(uint32_t ab, int tid, int ch) {
    const char* src = (const char*)g_Bimg4 + (size_t)ch * 65536;
    uint32_t dst = ab + BBUF_OFF + (uint32_t)(ch & 1) * 65536u;
    #pragma unroll 2
    for (int i = tid; i < 4096; i += 512)
        CPASYNC16(dst + (uint32_t)i * 16u, src + (size_t)i * 16);
    CPCOMMIT();
}

// ---------------------------------------------------------------------------
// Main HMMA distance kernel: 512 threads = 16 warps (4M x 4N), warp 32x32.
// A arrives pre-packed via cp.async; B double-buffered via cp.async.
__global__ void __launch_bounds__(512, 1)
k_main_mma() {
    extern __shared__ char dsm[];
    uint32_t raw = s2u(dsm);
    uint32_t ab  = (raw + 1023u) & ~1023u;
    char* sm = dsm + (ab - raw);

    const int tid  = threadIdx.x;
    const int lane = tid & 31, w = tid >> 5;
    const int gid  = lane >> 2, tig = lane & 3;
    const int wm   = w >> 2,  wn = w & 3;
    const int t    = blockIdx.x;

    float* esq_s = (float*)(sm + ESQ_OFF);
    float* zsq_s = (float*)(sm + ZSQ_OFF);
    int*   cnt_s = (int*)(sm + CNT_OFF);
    int*   rb_s  = (int*)(sm + ROWB_OFF);
    int*   cand_s = (int*)(sm + CAND_OFF);

    // A image + first two B chunks in flight
    {
        const char* srcA = (const char*)g_Aimg4 + (size_t)t * 65536;
        #pragma unroll 2
        for (int i = tid; i < 4096; i += 512)
            CPASYNC16(ab + A_OFF + (uint32_t)i * 16u, srcA + (size_t)i * 16);
        CPCOMMIT();
    }
    prefetch_chunk(ab, tid, 0);
    prefetch_chunk(ab, tid, 1);

    for (int i = tid; i < KCODES; i += 512) esq_s[i] = g_esq[i];
    if (tid < 128) {
        zsq_s[tid] = g_zsq[t * 128 + tid];
        cnt_s[tid] = 0;
        rb_s[tid]  = 0x7F7FFFFF;      // +FLT_MAX as int
    }
    __syncthreads();

    float zs[4];
    #pragma unroll
    for (int mt = 0; mt < 2; ++mt)
        #pragma unroll
        for (int hf = 0; hf < 2; ++hf)
            zs[mt * 2 + hf] = zsq_s[wm * 32 + mt * 16 + hf * 8 + gid];

    const uint32_t Abase = ab + A_OFF + (uint32_t)(wm * 32) * 512u;
    const int grp = lane >> 3, lr = lane & 7;

    for (int ch = 0; ch < 8; ++ch) {
        if (ch == 7) { CPWAIT0(); } else { CPWAIT1(); }
        __syncthreads();
        const uint32_t Bbase = ab + BBUF_OFF + (uint32_t)(ch & 1) * 65536u
                             + (uint32_t)(wn * 32) * 512u;
        float acc[2][4][4];
        #pragma unroll
        for (int mt = 0; mt < 2; ++mt)
            #pragma unroll
            for (int nt = 0; nt < 4; ++nt)
                #pragma unroll
                for (int q = 0; q < 4; ++q) acc[mt][nt][q] = 0.0f;

        #pragma unroll
        for (int kk = 0; kk < 16; ++kk) {
            uint32_t aR[2][4], bR[2][4];
            int ac16 = 2 * kk + (grp >> 1);
            int arow = (grp & 1) * 8 + lr;
            uint32_t axor = (uint32_t)((ac16 ^ lr) << 4);
            #pragma unroll
            for (int mt = 0; mt < 2; ++mt) {
                uint32_t addr = Abase + (uint32_t)(mt * 16 + arow) * 512u + axor;
                LDSM4(aR[mt][0], aR[mt][1], aR[mt][2], aR[mt][3], addr);
            }
            int bc16  = 2 * kk + (grp & 1);
            int bcode = (grp >> 1) * 8 + lr;
            uint32_t bxor = (uint32_t)((bc16 ^ lr) << 4);
            #pragma unroll
            for (int ntp = 0; ntp < 2; ++ntp) {
                uint32_t addr = Bbase + (uint32_t)(ntp * 16 + bcode) * 512u + bxor;
                LDSM4(bR[ntp][0], bR[ntp][1], bR[ntp][2], bR[ntp][3], addr);
            }
            #pragma unroll
            for (int mt = 0; mt < 2; ++mt)
                #pragma unroll
                for (int nt = 0; nt < 4; ++nt)
                    MMA16816(acc[mt][nt], aR[mt],
                             bR[nt >> 1][(nt & 1) * 2],
                             bR[nt >> 1][(nt & 1) * 2 + 1]);
        }

        // ---- epilogue: acc -> d in place; row min; candidate capture ----
        float es[8];
        #pragma unroll
        for (int nt = 0; nt < 4; ++nt)
            #pragma unroll
            for (int c01 = 0; c01 < 2; ++c01)
                es[nt * 2 + c01] = esq_s[ch * 128 + wn * 32 + nt * 8 + 2 * tig + c01];

        #pragma unroll
        for (int mt = 0; mt < 2; ++mt)
            #pragma unroll
            for (int nt = 0; nt < 4; ++nt)
                #pragma unroll
                for (int q = 0; q < 4; ++q)
                    acc[mt][nt][q] = fmaf(-2.0f, acc[mt][nt][q],
                                          zs[mt * 2 + (q >> 1)] + es[nt * 2 + (q & 1)]);

        #pragma unroll
        for (int mt = 0; mt < 2; ++mt)
            #pragma unroll
            for (int hf = 0; hf < 2; ++hf) {
                float mn = FLT_BIG;
                #pragma unroll
                for (int nt = 0; nt < 4; ++nt)
                    #pragma unroll
                    for (int c01 = 0; c01 < 2; ++c01) {
                        float d = acc[mt][nt][hf * 2 + c01];
                        if (d < mn) mn = d;
                    }
                #pragma unroll
                for (int o = 1; o <= 2; o <<= 1)
                    mn = fminf(mn, __shfl_xor_sync(0xFFFFFFFFu, mn, o));
                if (tig == 0) {
                    int rloc = wm * 32 + mt * 16 + hf * 8 + gid;
                    atomicMin(&rb_s[rloc], __float_as_int(mn));  // d > 0 always
                }
            }
        __syncthreads();

        #pragma unroll
        for (int mt = 0; mt < 2; ++mt)
            #pragma unroll
            for (int hf = 0; hf < 2; ++hf) {
                int rloc = wm * 32 + mt * 16 + hf * 8 + gid;
                float thr = __int_as_float(rb_s[rloc]) + EPS_CAND;
                #pragma unroll
                for (int nt = 0; nt < 4; ++nt)
                    #pragma unroll
                    for (int c01 = 0; c01 < 2; ++c01) {
                        float d = acc[mt][nt][hf * 2 + c01];
                        if (d <= thr) {
                            int pos = atomicAdd(&cnt_s[rloc], 1);
                            if (pos < CANDCAP)
                                cand_s[rloc * CANDCAP + pos] =
                                    ch * 128 + wn * 32 + nt * 8 + 2 * tig + c01;
                        }
                    }
            }
        __syncthreads();
        if (ch < 6) prefetch_chunk(ab, tid, ch + 2);
    }
    __syncthreads();
    if (tid < 128) g_cnt[t * 128 + tid] = cnt_s[tid];
    for (int i = tid; i < 128 * CANDCAP; i += 512)
        g_cand[(size_t)(t * 128) * CANDCAP + i] = cand_s[i];
}

// ---------------------------------------------------------------------------
// Refine: warp per row, lane per candidate; EXACT sequential fp32 chain
// (bit-identical to verified selection). Lexicographic (d, k) min.
__global__ void __launch_bounds__(256, 4)
k_refine(const float* __restrict__ emb) {
    __shared__ float zs[8][CHAN];
    int tid = threadIdx.x, lid = tid & 31, wrp = tid >> 5;
    int n = blockIdx.x * 8 + wrp;

    {   // stage z row (coalesced: 64 float4 per warp)
        const float4* zr4 = (const float4*)(g_zt + (size_t)n * CHAN);
        float4* zd4 = (float4*)zs[wrp];
        zd4[lid]      = zr4[lid];
        zd4[lid + 32] = zr4[lid + 32];
    }
    __syncwarp();

    float zsv = g_zsq[n];
    int cnt = g_cnt[n];
    const float* zrow = zs[wrp];

    float bd = FLT_BIG;
    int bk = 1 << 30;

    if (cnt <= CANDCAP) {
        if (lid < cnt) {
            int k = g_cand[(size_t)n * CANDCAP + lid];
            const float* ep = emb + (size_t)k * CHAN;
            float acc = 0.0f;
            #pragma unroll 8
            for (int c = 0; c < CHAN; ++c)
                acc = fmaf(zrow[c], ep[c], acc);
            bd = __fmaf_rn(-2.0f, acc, zsv + g_esq[k]);
            bk = k;
        }
    } else {
        for (int k = lid; k < KCODES; k += 32) {
            const float* ep = emb + (size_t)k * CHAN;
            float acc = 0.0f;
            #pragma unroll 8
            for (int c = 0; c < CHAN; ++c)
                acc = fmaf(zrow[c], ep[c], acc);
            float d = __fmaf_rn(-2.0f, acc, zsv + g_esq[k]);
            if (d < bd || (d == bd && k < bk)) { bd = d; bk = k; }
        }
    }
    #pragma unroll
    for (int o = 16; o; o >>= 1) {
        float od = __shfl_down_sync(0xFFFFFFFFu, bd, o);
        int   ok = __shfl_down_sync(0xFFFFFFFFu, bk, o);
        if (od < bd || (od == bd && ok < bk)) { bd = od; bk = ok; }
    }
    if (lid == 0) g_idx[n] = bk;
}

// ---------------------------------------------------------------------------
// Output + loss partials, float4 path. Straight-through mimic per element:
// df = q - z; out = z + df (elementwise identical to the verified kernel).
__global__ void k_out(const float* __restrict__ z, const float* __restrict__ emb,
                      float* __restrict__ out) {
    __shared__ int   sidx[TILE_R];
    __shared__ float qs_t[64 * 132];       // [c_local][hw], padded
    __shared__ float red[256];

    int t = blockIdx.x, cg = blockIdx.y;
    int b = t >> 3, hw0 = (t & 7) << 7;
    int tid = threadIdx.x;

    if (tid < TILE_R) sidx[tid] = g_idx[t * TILE_R + tid];
    __syncthreads();

    {   // gather emb rows -> transposed smem
        int row = tid >> 1, half = tid & 1;
        const float4* e4 = (const float4*)(emb + (size_t)sidx[row] * CHAN + cg * 64);
        #pragma unroll
        for (int q = 0; q < 8; ++q) {
            float4 v = e4[half * 8 + q];
            int c0 = half * 32 + q * 4;
            qs_t[(c0 + 0) * 132 + row] = v.x;
            qs_t[(c0 + 1) * 132 + row] = v.y;
            qs_t[(c0 + 2) * 132 + row] = v.z;
            qs_t[(c0 + 3) * 132 + row] = v.w;
        }
    }
    __syncthreads();

    float accum = 0.0f;
    int hw4 = (tid & 31) << 2, cbase = tid >> 5;
    #pragma unroll
    for (int it = 0; it < 8; ++it) {
        int cl = it * 8 + cbase;
        size_t off = ((size_t)(b * CHAN + cg * 64 + cl)) * HWSZ + hw0 + hw4;
        float4 zv = *(const float4*)(z + off);
        float4 qv = *(const float4*)(&qs_t[cl * 132 + hw4]);
        float dx = qv.x - zv.x, dy = qv.y - zv.y;
        float dz = qv.z - zv.z, dw = qv.w - zv.w;
        float4 ov;
        ov.x = zv.x + dx; ov.y = zv.y + dy;
        ov.z = zv.z + dz; ov.w = zv.w + dw;
        *(float4*)(out + off) = ov;
        accum = fmaf(dx, dx, accum); accum = fmaf(dy, dy, accum);
        accum = fmaf(dz, dz, accum); accum = fmaf(dw, dw, accum);
    }
    red[tid] = accum;
    __syncthreads();
    #pragma unroll
    for (int s = 128; s > 0; s >>= 1) {
        if (tid < s) red[tid] += red[tid + s];
        __syncthreads();
    }
    if (tid == 0) g_part[t * 4 + cg] = red[0];
}

// loss = m + 0.25*m, m = mean(df^2); fixed-order deterministic reduction.
__global__ void k_final(float* __restrict__ out) {
    __shared__ float red[256];
    int tid = threadIdx.x;
    float a = 0.0f;
    for (int i = tid; i < NPART; i += 256) a += g_part[i];
    red[tid] = a;
    __syncthreads();
    #pragma unroll
    for (int s = 128; s > 0; s >>= 1) {
        if (tid < s) red[tid] += red[tid + s];
        __syncthreads();
    }
    if (tid == 0) {
        float m = red[0] / 16777216.0f;
        out[16777216] = m + 0.25f * m;
    }
}

// ---------------------------------------------------------------------------
extern "C" void kernel_launch(void* const* d_in, const int* in_sizes, int n_in,
                              void* d_out, int out_size) {
    const float* z   = (const float*)d_in[0];   // [64,256,32,32]
    const float* emb = (const float*)d_in[1];   // [1024,256]
    float* out = (float*)d_out;

    cudaFuncSetAttribute(k_main_mma, cudaFuncAttributeMaxDynamicSharedMemorySize,
                         SMEM_REQ);

    k_embprep<<<KCODES, 128>>>(emb);
    k_zprep<<<NTILES, 256>>>(z);
    k_main_mma<<<NTILES, 512, SMEM_REQ>>>();
    k_refine<<<NROWS / 8, 256>>>(emb);
    dim3 g(NTILES, 4);
    k_out<<<g, 256>>>(z, emb, out);
    k_final<<<1, 256>>>(out);
}

// round 16
// speedup vs baseline: 2.3907x; 1.2231x over previous
#include <cuda_runtime.h>
#include <cuda_bf16.h>
#include <cstdint>

// ---------------------------------------------------------------------------
// Problem constants
#define BATCH   64
#define CHAN    256
#define HWSZ    1024
#define NROWS   65536
#define KCODES  1024
#define TILE_R  128
#define NTILES  512
#define NPART   2048
#define EPS_CAND 4e-3f
#define CANDCAP  16
#define FLT_BIG  3.4028235e38f

// SMEM layout for k_main (relative to 1024-aligned base)
#define A_OFF    0          // 128 rows x 256 c bf16, swizzled: 65536 B
#define BBUF_OFF 65536      // two B buffers, 65536 B each
#define ESQ_OFF  196608     // 1024 f32
#define ZSQ_OFF  200704     // 128 f32
#define CNT_OFF  201216     // 128 int
#define ROWB_OFF 201728     // 128 int (float-as-int running row min)
#define CAND_OFF 202240     // 128*16 int = 8192 B
#define SMEM_END 210432
#define SMEM_REQ (SMEM_END + 1024)

// ---------------------------------------------------------------------------
// Scratch (static device globals; no runtime allocation)
__device__ float g_esq[KCODES];
__device__ float g_zsq[NROWS];
__device__ int   g_idx[NROWS];
__device__ int   g_cnt[NROWS];
__device__ float g_part[NPART];
__device__ int   g_cand[(size_t)NROWS * CANDCAP];
__device__ uint4 g_Bimg4[8 * 4096];            // 8 chunks x 64KB swizzled B
__device__ uint4 g_Aimg4[NTILES * 4096];       // per-tile 64KB swizzled A, 32MB
__device__ float g_zt[(size_t)NROWS * CHAN];   // transposed z [n][c], 64MB

// ---------------------------------------------------------------------------
// PTX helpers — base-sm_103-safe (sm_80-era instructions only)
__device__ __forceinline__ uint32_t s2u(const void* p) {
    uint32_t a;
    asm("{ .reg .u64 t; cvta.to.shared.u64 t, %1; cvt.u32.u64 %0, t; }"
        : "=r"(a) : "l"(p));
    return a;
}
#define LDSM4(r0, r1, r2, r3, addr) \
    asm volatile("ldmatrix.sync.aligned.m8n8.x4.shared.b16 {%0,%1,%2,%3}, [%4];" \
        : "=r"(r0), "=r"(r1), "=r"(r2), "=r"(r3) : "r"(addr))
#define MMA16816(d, a, b0, b1) \
    asm volatile("mma.sync.aligned.m16n8k16.row.col.f32.bf16.bf16.f32 " \
        "{%0,%1,%2,%3}, {%4,%5,%6,%7}, {%8,%9}, {%0,%1,%2,%3};" \
        : "+f"((d)[0]), "+f"((d)[1]), "+f"((d)[2]), "+f"((d)[3]) \
        : "r"((a)[0]), "r"((a)[1]), "r"((a)[2]), "r"((a)[3]), "r"(b0), "r"(b1))
#define CPASYNC16(dst, src) \
    asm volatile("cp.async.cg.shared.global [%0], [%1], 16;" :: "r"(dst), "l"(src))
#define CPCOMMIT() asm volatile("cp.async.commit_group;" ::: "memory")
#define CPWAIT1()  asm volatile("cp.async.wait_group 1;" ::: "memory")
#define CPWAIT0()  asm volatile("cp.async.wait_group 0;" ::: "memory")

// ---------------------------------------------------------------------------
// Codebook prep: pack bf16 swizzled B images + e_sq sequential chain.
__global__ void k_embprep(const float* __restrict__ emb) {
    int k  = blockIdx.x;
    int c  = threadIdx.x * 2;
    float f0 = emb[(size_t)k * CHAN + c];
    float f1 = emb[(size_t)k * CHAN + c + 1];
    __nv_bfloat162 h2 = __floats2bfloat162_rn(f0, f1);
    uint32_t u = *(uint32_t*)&h2;
    int chunk = k >> 7, cl = k & 127;
    int c16 = c >> 3;
    uint32_t addr = (uint32_t)cl * 512u
                  + (uint32_t)((c16 ^ (cl & 7)) << 4) + (uint32_t)(c & 7) * 2u;
    ((uint32_t*)g_Bimg4)[chunk * 16384 + (addr >> 2)] = u;

    if (threadIdx.x == 0) {      // exact sequential-c fp32 chain (verified)
        const float* row = emb + (size_t)k * CHAN;
        float acc = 0.0f;
        #pragma unroll 8
        for (int cc = 0; cc < CHAN; ++cc) acc = fmaf(row[cc], row[cc], acc);
        g_esq[k] = acc;
    }
}

// ---------------------------------------------------------------------------
// z prep: transpose z -> z_t[n][c]; then z_sq (exact chain, same values/order
// as the verified kernel) and the swizzled bf16 A-image, both from z_t.
__global__ void k_zprep(const float* __restrict__ z) {
    __shared__ float S[32 * 132];
    int t = blockIdx.x;
    int b = t >> 3, hw0 = (t & 7) << 7;
    int tid = threadIdx.x;
    const float* zb = z + (size_t)b * CHAN * HWSZ + hw0;

    // Phase 1: transpose to g_zt
    for (int g = 0; g < 8; ++g) {
        #pragma unroll
        for (int it = 0; it < 4; ++it) {
            int cl = it * 8 + (tid >> 5);
            int r4 = (tid & 31) << 2;
            float4 v = *(const float4*)(zb + (size_t)(g * 32 + cl) * HWSZ + r4);
            *(float4*)(S + cl * 132 + r4) = v;
        }
        __syncthreads();
        int r = tid >> 1, half = tid & 1;
        float* dst = g_zt + ((size_t)(t * TILE_R + r)) * CHAN + g * 32 + half * 16;
        #pragma unroll
        for (int q = 0; q < 4; ++q) {
            int c0 = half * 16 + q * 4;
            float4 v;
            v.x = S[(c0 + 0) * 132 + r];
            v.y = S[(c0 + 1) * 132 + r];
            v.z = S[(c0 + 2) * 132 + r];
            v.w = S[(c0 + 3) * 132 + r];
            *(float4*)(dst + q * 4) = v;
        }
        __syncthreads();
    }

    // Phase 2a: z_sq — exact sequential fp32 chain over ascending c
    if (tid < TILE_R) {
        const float* zr = g_zt + (size_t)(t * TILE_R + tid) * CHAN;
        float acc = 0.0f;
        #pragma unroll 8
        for (int c = 0; c < CHAN; ++c) acc = fmaf(zr[c], zr[c], acc);
        g_zsq[t * TILE_R + tid] = acc;
    }

    // Phase 2b: bf16 swizzled A-image (64KB per tile) to global
    #pragma unroll
    for (int i = 0; i < 16; ++i) {
        int j = tid + i * 256;              // 0..4095
        int row = j >> 5, c16 = j & 31;
        const float4* zr4 = (const float4*)(g_zt
            + (size_t)(t * TILE_R + row) * CHAN + c16 * 8);
        float4 a = zr4[0], c = zr4[1];
        uint32_t u[4];
        __nv_bfloat162 h0 = __floats2bfloat162_rn(a.x, a.y); u[0] = *(uint32_t*)&h0;
        __nv_bfloat162 h1 = __floats2bfloat162_rn(a.z, a.w); u[1] = *(uint32_t*)&h1;
        __nv_bfloat162 h2 = __floats2bfloat162_rn(c.x, c.y); u[2] = *(uint32_t*)&h2;
        __nv_bfloat162 h3 = __floats2bfloat162_rn(c.z, c.w); u[3] = *(uint32_t*)&h3;
        uint32_t off = (uint32_t)row * 512u
                     + (uint32_t)((c16 ^ (row & 7)) << 4);
        g_Aimg4[(size_t)t * 4096 + (off >> 4)] = make_uint4(u[0], u[1], u[2], u[3]);
    }
}

// ---------------------------------------------------------------------------
__device__ __forceinline__ void prefetch_chunk(uint32_t ab, int tid, int ch) {
    const char* src = (const char*)g_Bimg4 + (size_t)ch * 65536;
    uint32_t dst = ab + BBUF_OFF + (uint32_t)(ch & 1) * 65536u;
    #pragma unroll 2
    for (int i = tid; i < 4096; i += 512)
        CPASYNC16(dst + (uint32_t)i * 16u, src + (size_t)i * 16);
    CPCOMMIT();
}

// ---------------------------------------------------------------------------
// Main HMMA distance kernel: 512 threads = 16 warps (4M x 4N), warp 32x32.
// A arrives pre-packed via cp.async; B double-buffered via cp.async.
__global__ void __launch_bounds__(512, 1)
k_main_mma() {
    extern __shared__ char dsm[];
    uint32_t raw = s2u(dsm);
    uint32_t ab  = (raw + 1023u) & ~1023u;
    char* sm = dsm + (ab - raw);

    const int tid  = threadIdx.x;
    const int lane = tid & 31, w = tid >> 5;
    const int gid  = lane >> 2, tig = lane & 3;
    const int wm   = w >> 2,  wn = w & 3;
    const int t    = blockIdx.x;

    float* esq_s = (float*)(sm + ESQ_OFF);
    float* zsq_s = (float*)(sm + ZSQ_OFF);
    int*   cnt_s = (int*)(sm + CNT_OFF);
    int*   rb_s  = (int*)(sm + ROWB_OFF);
    int*   cand_s = (int*)(sm + CAND_OFF);

    // A image + first two B chunks in flight
    {
        const char* srcA = (const char*)g_Aimg4 + (size_t)t * 65536;
        #pragma unroll 2
        for (int i = tid; i < 4096; i += 512)
            CPASYNC16(ab + A_OFF + (uint32_t)i * 16u, srcA + (size_t)i * 16);
        CPCOMMIT();
    }
    prefetch_chunk(ab, tid, 0);
    prefetch_chunk(ab, tid, 1);

    for (int i = tid; i < KCODES; i += 512) esq_s[i] = g_esq[i];
    if (tid < 128) {
        zsq_s[tid] = g_zsq[t * 128 + tid];
        cnt_s[tid] = 0;
        rb_s[tid]  = 0x7F7FFFFF;      // +FLT_MAX as int
    }
    __syncthreads();

    float zs[4];
    #pragma unroll
    for (int mt = 0; mt < 2; ++mt)
        #pragma unroll
        for (int hf = 0; hf < 2; ++hf)
            zs[mt * 2 + hf] = zsq_s[wm * 32 + mt * 16 + hf * 8 + gid];

    const uint32_t Abase = ab + A_OFF + (uint32_t)(wm * 32) * 512u;
    const int grp = lane >> 3, lr = lane & 7;

    for (int ch = 0; ch < 8; ++ch) {
        if (ch == 7) { CPWAIT0(); } else { CPWAIT1(); }
        __syncthreads();
        const uint32_t Bbase = ab + BBUF_OFF + (uint32_t)(ch & 1) * 65536u
                             + (uint32_t)(wn * 32) * 512u;
        float acc[2][4][4];
        #pragma unroll
        for (int mt = 0; mt < 2; ++mt)
            #pragma unroll
            for (int nt = 0; nt < 4; ++nt)
                #pragma unroll
                for (int q = 0; q < 4; ++q) acc[mt][nt][q] = 0.0f;

        #pragma unroll
        for (int kk = 0; kk < 16; ++kk) {
            uint32_t aR[2][4], bR[2][4];
            int ac16 = 2 * kk + (grp >> 1);
            int arow = (grp & 1) * 8 + lr;
            uint32_t axor = (uint32_t)((ac16 ^ lr) << 4);
            #pragma unroll
            for (int mt = 0; mt < 2; ++mt) {
                uint32_t addr = Abase + (uint32_t)(mt * 16 + arow) * 512u + axor;
                LDSM4(aR[mt][0], aR[mt][1], aR[mt][2], aR[mt][3], addr);
            }
            int bc16  = 2 * kk + (grp & 1);
            int bcode = (grp >> 1) * 8 + lr;
            uint32_t bxor = (uint32_t)((bc16 ^ lr) << 4);
            #pragma unroll
            for (int ntp = 0; ntp < 2; ++ntp) {
                uint32_t addr = Bbase + (uint32_t)(ntp * 16 + bcode) * 512u + bxor;
                LDSM4(bR[ntp][0], bR[ntp][1], bR[ntp][2], bR[ntp][3], addr);
            }
            #pragma unroll
            for (int mt = 0; mt < 2; ++mt)
                #pragma unroll
                for (int nt = 0; nt < 4; ++nt)
                    MMA16816(acc[mt][nt], aR[mt],
                             bR[nt >> 1][(nt & 1) * 2],
                             bR[nt >> 1][(nt & 1) * 2 + 1]);
        }

        // ---- epilogue: acc -> d in place; row min; candidate capture ----
        float es[8];
        #pragma unroll
        for (int nt = 0; nt < 4; ++nt)
            #pragma unroll
            for (int c01 = 0; c01 < 2; ++c01)
                es[nt * 2 + c01] = esq_s[ch * 128 + wn * 32 + nt * 8 + 2 * tig + c01];

        #pragma unroll
        for (int mt = 0; mt < 2; ++mt)
            #pragma unroll
            for (int nt = 0; nt < 4; ++nt)
                #pragma unroll
                for (int q = 0; q < 4; ++q)
                    acc[mt][nt][q] = fmaf(-2.0f, acc[mt][nt][q],
                                          zs[mt * 2 + (q >> 1)] + es[nt * 2 + (q & 1)]);

        #pragma unroll
        for (int mt = 0; mt < 2; ++mt)
            #pragma unroll
            for (int hf = 0; hf < 2; ++hf) {
                float mn = FLT_BIG;
                #pragma unroll
                for (int nt = 0; nt < 4; ++nt)
                    #pragma unroll
                    for (int c01 = 0; c01 < 2; ++c01) {
                        float d = acc[mt][nt][hf * 2 + c01];
                        if (d < mn) mn = d;
                    }
                #pragma unroll
                for (int o = 1; o <= 2; o <<= 1)
                    mn = fminf(mn, __shfl_xor_sync(0xFFFFFFFFu, mn, o));
                if (tig == 0) {
                    int rloc = wm * 32 + mt * 16 + hf * 8 + gid;
                    atomicMin(&rb_s[rloc], __float_as_int(mn));  // d > 0 always
                }
            }
        __syncthreads();

        #pragma unroll
        for (int mt = 0; mt < 2; ++mt)
            #pragma unroll
            for (int hf = 0; hf < 2; ++hf) {
                int rloc = wm * 32 + mt * 16 + hf * 8 + gid;
                float thr = __int_as_float(rb_s[rloc]) + EPS_CAND;
                #pragma unroll
                for (int nt = 0; nt < 4; ++nt)
                    #pragma unroll
                    for (int c01 = 0; c01 < 2; ++c01) {
                        float d = acc[mt][nt][hf * 2 + c01];
                        if (d <= thr) {
                            int pos = atomicAdd(&cnt_s[rloc], 1);
                            if (pos < CANDCAP)
                                cand_s[rloc * CANDCAP + pos] =
                                    ch * 128 + wn * 32 + nt * 8 + 2 * tig + c01;
                        }
                    }
            }
        __syncthreads();
        if (ch < 6) prefetch_chunk(ab, tid, ch + 2);
    }
    __syncthreads();
    if (tid < 128) g_cnt[t * 128 + tid] = cnt_s[tid];
    for (int i = tid; i < 128 * CANDCAP; i += 512)
        g_cand[(size_t)(t * 128) * CANDCAP + i] = cand_s[i];
}

// ---------------------------------------------------------------------------
// Refine v2: warp per row.
//  * cnt==1 fast path: the candidate list provably contains the exact argmin
//    (EPS is ~12x the max approx error, and any element beating a previous
//    candidate is captured in its own chunk), so a singleton IS the argmin.
//  * cnt>1: lane per candidate, float4 loads; fmaf chain over ascending c is
//    bit-identical to the verified sequential chain. Lexicographic (d,k) min.
__global__ void __launch_bounds__(256, 4)
k_refine(const float* __restrict__ emb) {
    __shared__ __align__(16) float zs[8][CHAN];
    int tid = threadIdx.x, lid = tid & 31, wrp = tid >> 5;
    int n = blockIdx.x * 8 + wrp;

    int cnt = g_cnt[n];
    if (cnt == 1) {
        if (lid == 0) g_idx[n] = g_cand[(size_t)n * CANDCAP];
        return;
    }

    {   // stage z row (coalesced: 64 float4 per warp)
        const float4* zr4 = (const float4*)(g_zt + (size_t)n * CHAN);
        float4* zd4 = (float4*)zs[wrp];
        zd4[lid]      = zr4[lid];
        zd4[lid + 32] = zr4[lid + 32];
    }
    __syncwarp();

    float zsv = g_zsq[n];
    const float* zrow = zs[wrp];

    float bd = FLT_BIG;
    int bk = 1 << 30;

    if (cnt <= CANDCAP) {
        if (lid < cnt) {
            int k = g_cand[(size_t)n * CANDCAP + lid];
            const float4* ep4 = (const float4*)(emb + (size_t)k * CHAN);
            float acc = 0.0f;
            #pragma unroll 8
            for (int c4 = 0; c4 < 64; ++c4) {
                float4 e  = __ldg(ep4 + c4);
                float4 zq = *(const float4*)(zrow + c4 * 4);
                acc = fmaf(zq.x, e.x, acc);
                acc = fmaf(zq.y, e.y, acc);
                acc = fmaf(zq.z, e.z, acc);
                acc = fmaf(zq.w, e.w, acc);
            }
            bd = __fmaf_rn(-2.0f, acc, zsv + g_esq[k]);
            bk = k;
        }
    } else {
        // overflow fallback: exact scan of all codes (float4, same chain)
        for (int k = lid; k < KCODES; k += 32) {
            const float4* ep4 = (const float4*)(emb + (size_t)k * CHAN);
            float acc = 0.0f;
            #pragma unroll 8
            for (int c4 = 0; c4 < 64; ++c4) {
                float4 e  = __ldg(ep4 + c4);
                float4 zq = *(const float4*)(zrow + c4 * 4);
                acc = fmaf(zq.x, e.x, acc);
                acc = fmaf(zq.y, e.y, acc);
                acc = fmaf(zq.z, e.z, acc);
                acc = fmaf(zq.w, e.w, acc);
            }
            float d = __fmaf_rn(-2.0f, acc, zsv + g_esq[k]);
            if (d < bd || (d == bd && k < bk)) { bd = d; bk = k; }
        }
    }
    #pragma unroll
    for (int o = 16; o; o >>= 1) {
        float od = __shfl_down_sync(0xFFFFFFFFu, bd, o);
        int   ok = __shfl_down_sync(0xFFFFFFFFu, bk, o);
        if (od < bd || (od == bd && ok < bk)) { bd = od; bk = ok; }
    }
    if (lid == 0) g_idx[n] = bk;
}

// ---------------------------------------------------------------------------
// Output + loss partials, float4 path. Straight-through mimic per element:
// df = q - z; out = z + df (elementwise identical to the verified kernel).
__global__ void k_out(const float* __restrict__ z, const float* __restrict__ emb,
                      float* __restrict__ out) {
    __shared__ int   sidx[TILE_R];
    __shared__ float qs_t[64 * 132];       // [c_local][hw], padded
    __shared__ float red[256];

    int t = blockIdx.x, cg = blockIdx.y;
    int b = t >> 3, hw0 = (t & 7) << 7;
    int tid = threadIdx.x;

    if (tid < TILE_R) sidx[tid] = g_idx[t * TILE_R + tid];
    __syncthreads();

    {   // gather emb rows -> transposed smem
        int row = tid >> 1, half = tid & 1;
        const float4* e4 = (const float4*)(emb + (size_t)sidx[row] * CHAN + cg * 64);
        #pragma unroll
        for (int q = 0; q < 8; ++q) {
            float4 v = e4[half * 8 + q];
            int c0 = half * 32 + q * 4;
            qs_t[(c0 + 0) * 132 + row] = v.x;
            qs_t[(c0 + 1) * 132 + row] = v.y;
            qs_t[(c0 + 2) * 132 + row] = v.z;
            qs_t[(c0 + 3) * 132 + row] = v.w;
        }
    }
    __syncthreads();

    float accum = 0.0f;
    int hw4 = (tid & 31) << 2, cbase = tid >> 5;
    #pragma unroll
    for (int it = 0; it < 8; ++it) {
        int cl = it * 8 + cbase;
        size_t off = ((size_t)(b * CHAN + cg * 64 + cl)) * HWSZ + hw0 + hw4;
        float4 zv = *(const float4*)(z + off);
        float4 qv = *(const float4*)(&qs_t[cl * 132 + hw4]);
        float dx = qv.x - zv.x, dy = qv.y - zv.y;
        float dz = qv.z - zv.z, dw = qv.w - zv.w;
        float4 ov;
        ov.x = zv.x + dx; ov.y = zv.y + dy;
        ov.z = zv.z + dz; ov.w = zv.w + dw;
        *(float4*)(out + off) = ov;
        accum = fmaf(dx, dx, accum); accum = fmaf(dy, dy, accum);
        accum = fmaf(dz, dz, accum); accum = fmaf(dw, dw, accum);
    }
    red[tid] = accum;
    __syncthreads();
    #pragma unroll
    for (int s = 128; s > 0; s >>= 1) {
        if (tid < s) red[tid] += red[tid + s];
        __syncthreads();
    }
    if (tid == 0) g_part[t * 4 + cg] = red[0];
}

// loss = m + 0.25*m, m = mean(df^2); fixed-order deterministic reduction.
__global__ void k_final(float* __restrict__ out) {
    __shared__ float red[256];
    int tid = threadIdx.x;
    float a = 0.0f;
    for (int i = tid; i < NPART; i += 256) a += g_part[i];
    red[tid] = a;
    __syncthreads();
    #pragma unroll
    for (int s = 128; s > 0; s >>= 1) {
        if (tid < s) red[tid] += red[tid + s];
        __syncthreads();
    }
    if (tid == 0) {
        float m = red[0] / 16777216.0f;
        out[16777216] = m + 0.25f * m;
    }
}

// ---------------------------------------------------------------------------
extern "C" void kernel_launch(void* const* d_in, const int* in_sizes, int n_in,
                              void* d_out, int out_size) {
    const float* z   = (const float*)d_in[0];   // [64,256,32,32]
    const float* emb = (const float*)d_in[1];   // [1024,256]
    float* out = (float*)d_out;

    cudaFuncSetAttribute(k_main_mma, cudaFuncAttributeMaxDynamicSharedMemorySize,
                         SMEM_REQ);

    k_embprep<<<KCODES, 128>>>(emb);
    k_zprep<<<NTILES, 256>>>(z);
    k_main_mma<<<NTILES, 512, SMEM_REQ>>>();
    k_refine<<<NROWS / 8, 256>>>(emb);
    dim3 g(NTILES, 4);
    k_out<<<g, 256>>>(z, emb, out);
    k_final<<<1, 256>>>(out);
}